// round 1
// baseline (speedup 1.0000x reference)
#include <cuda_runtime.h>
#include <math.h>

// Problem constants
#define B_      4
#define S_      4096
#define DIN     1024
#define NC      1024            // combined hidden channels (fast 0..511 | slow 512..1023)
#define N1      2048            // GEMM1 output cols, interleaved: col 2c = z_c, col 2c+1 = h~_c
#define M_      (B_*S_)         // 16384 rows
#define LANES   (B_*NC)         // 4096 independent scan lanes
#define NCHUNK  64
#define LC      (S_/NCHUNK)     // 64 steps per chunk

// ---------------- scratch (static device globals; no allocations) ----------------
__device__ float  g_W1[DIN * N1];                 // packed weights, row-major [k][n]
__device__ float  g_b1[N1];                       // packed biases
__device__ float  g_Y[(size_t)M_ * N1];           // after GEMM1 epilogue: interleaved (a, b) pairs
__device__ float  g_h[(size_t)M_ * NC];           // h_combined
__device__ float2 g_Agg[NCHUNK * LANES];          // per-(chunk,lane) aggregates (A, B)
__device__ float  g_Carry[NCHUNK * LANES];        // carry entering each chunk

__device__ __forceinline__ float sigmoidf_(float x) {
    return 1.0f / (1.0f + __expf(-x));
}

// ---------------- weight/bias packing ----------------
// g_W1[k][2c+0] = z-weight for channel c (fast: W_zf, slow: W_zs)
// g_W1[k][2c+1] = h-weight for channel c (fast: W_hf, slow: W_hs)
__global__ void pack_w_kernel(const float* __restrict__ Wzf, const float* __restrict__ Whf,
                              const float* __restrict__ Wzs, const float* __restrict__ Whs,
                              const float* __restrict__ bzf, const float* __restrict__ bhf,
                              const float* __restrict__ bzs, const float* __restrict__ bhs) {
    int idx = blockIdx.x * blockDim.x + threadIdx.x;
    if (idx >= DIN * N1) return;
    int k = idx >> 11;          // / 2048
    int n = idx & (N1 - 1);
    int c = n >> 1;
    int hpart = n & 1;
    float v;
    if (c < 512) v = hpart ? Whf[k * 512 + c]        : Wzf[k * 512 + c];
    else         v = hpart ? Whs[k * 512 + (c-512)]  : Wzs[k * 512 + (c-512)];
    g_W1[idx] = v;
    if (idx < N1) {
        int cc = idx >> 1;
        int hp = idx & 1;
        float bv;
        if (cc < 512) bv = hp ? bhf[cc]       : bzf[cc];
        else          bv = hp ? bhs[cc - 512] : bzs[cc - 512];
        g_b1[idx] = bv;
    }
}

// ---------------- fp32 SIMT GEMM core: 128x128 block, BK=8, 256 threads, 8x8/thread ----------------
template <int N>
__device__ __forceinline__ void sgemm_body(const float* __restrict__ A,
                                           const float* __restrict__ Bmat,
                                           float acc[8][8], int bm, int bn) {
    const int K = 1024;
    __shared__ float As[8][128];   // transposed A tile: As[k][m]
    __shared__ float Bs[8][128];   // Bs[k][n]

    int tid  = threadIdx.x;
    int aRow = tid >> 1;            // 0..127
    int aCol = (tid & 1) << 2;      // 0 or 4
    int bRow = tid >> 5;            // 0..7
    int bCol = (tid & 31) << 2;     // 0..124
    int tx   = tid & 15;
    int ty   = tid >> 4;

    const float* Ap = A    + (size_t)(bm + aRow) * K + aCol;
    const float* Bp = Bmat + (size_t)bRow * N + bn + bCol;

#pragma unroll
    for (int i = 0; i < 8; i++)
#pragma unroll
        for (int j = 0; j < 8; j++) acc[i][j] = 0.0f;

    for (int k0 = 0; k0 < K; k0 += 8) {
        float4 av = *(const float4*)Ap;
        float4 bv = *(const float4*)Bp;
        As[aCol + 0][aRow] = av.x;
        As[aCol + 1][aRow] = av.y;
        As[aCol + 2][aRow] = av.z;
        As[aCol + 3][aRow] = av.w;
        *(float4*)&Bs[bRow][bCol] = bv;
        __syncthreads();
#pragma unroll
        for (int kk = 0; kk < 8; kk++) {
            float4 a0 = *(const float4*)&As[kk][ty * 4];
            float4 a1 = *(const float4*)&As[kk][64 + ty * 4];
            float4 b0 = *(const float4*)&Bs[kk][tx * 4];
            float4 b1 = *(const float4*)&Bs[kk][64 + tx * 4];
            float aa[8] = {a0.x, a0.y, a0.z, a0.w, a1.x, a1.y, a1.z, a1.w};
            float bb[8] = {b0.x, b0.y, b0.z, b0.w, b1.x, b1.y, b1.z, b1.w};
#pragma unroll
            for (int i = 0; i < 8; i++)
#pragma unroll
                for (int j = 0; j < 8; j++)
                    acc[i][j] = fmaf(aa[i], bb[j], acc[i][j]);
        }
        __syncthreads();
        Ap += 8;
        Bp += (size_t)8 * N;
    }
}

// GEMM1: Y_pre = x @ W1 + b1, fused epilogue -> (a, b) = (1 - sigmoid(zpre), sigmoid(zpre)*hpre)
__global__ __launch_bounds__(256) void gemm1_kernel(const float* __restrict__ x) {
    float acc[8][8];
    int bm = blockIdx.y * 128;
    int bn = blockIdx.x * 128;
    sgemm_body<N1>(x, g_W1, acc, bm, bn);

    int tx = threadIdx.x & 15;
    int ty = threadIdx.x >> 4;
#pragma unroll
    for (int i = 0; i < 8; i++) {
        int m = bm + ((i < 4) ? (ty * 4 + i) : (64 + ty * 4 + i - 4));
#pragma unroll
        for (int g = 0; g < 2; g++) {
            int n0 = bn + g * 64 + tx * 4;       // multiple of 4 -> contains 2 (z,h) pairs
            float4 bia = *(const float4*)&g_b1[n0];
            float zp0 = acc[i][g * 4 + 0] + bia.x;
            float hp0 = acc[i][g * 4 + 1] + bia.y;
            float zp1 = acc[i][g * 4 + 2] + bia.z;
            float hp1 = acc[i][g * 4 + 3] + bia.w;
            float z0 = sigmoidf_(zp0);
            float z1 = sigmoidf_(zp1);
            float4 o = make_float4(1.0f - z0, z0 * hp0, 1.0f - z1, z1 * hp1);
            *(float4*)&g_Y[(size_t)m * N1 + n0] = o;
        }
    }
}

// ---------------- scan (3-phase chunked) ----------------
// Phase 1: per (lane, chunk) compute aggregate (A = prod a_t, B = local scan ending value from 0)
__global__ __launch_bounds__(256) void scan_phase1() {
    int lane = blockIdx.x * blockDim.x + threadIdx.x;   // 0..4095
    int j    = blockIdx.y;                              // chunk
    int b    = lane >> 10;
    int c    = lane & (NC - 1);
    const float2* Y2 = (const float2*)g_Y;              // [m][c] pairs
    size_t base = ((size_t)(b * S_ + j * LC)) * NC + c;
    float A = 1.0f, H = 0.0f;
#pragma unroll 8
    for (int t = 0; t < LC; t++) {
        float2 ab = Y2[base + (size_t)t * NC];
        A *= ab.x;
        H = fmaf(ab.x, H, ab.y);
    }
    g_Agg[j * LANES + lane] = make_float2(A, H);
}

// Phase 2: per lane, sequential combine over chunks; store carry entering each chunk
__global__ __launch_bounds__(256) void scan_phase2() {
    int lane = blockIdx.x * blockDim.x + threadIdx.x;
    float carry = 0.0f;
#pragma unroll
    for (int j = 0; j < NCHUNK; j++) {
        float2 e = g_Agg[j * LANES + lane];
        g_Carry[j * LANES + lane] = carry;
        carry = fmaf(e.x, carry, e.y);
    }
}

// Phase 3: re-scan each chunk with correct initial carry, write h_combined
__global__ __launch_bounds__(256) void scan_phase3() {
    int lane = blockIdx.x * blockDim.x + threadIdx.x;
    int j    = blockIdx.y;
    int b    = lane >> 10;
    int c    = lane & (NC - 1);
    const float2* Y2 = (const float2*)g_Y;
    size_t m0 = (size_t)(b * S_ + j * LC);
    size_t base = m0 * NC + c;
    float H = g_Carry[j * LANES + lane];
#pragma unroll 8
    for (int t = 0; t < LC; t++) {
        float2 ab = Y2[base + (size_t)t * NC];
        H = fmaf(ab.x, H, ab.y);
        g_h[(m0 + t) * NC + c] = H;
    }
}

// GEMM2: out = sigmoid(h @ W_g + b_g) * h
__global__ __launch_bounds__(256) void gemm2_kernel(const float* __restrict__ Wg,
                                                    const float* __restrict__ bg,
                                                    float* __restrict__ out) {
    float acc[8][8];
    int bm = blockIdx.y * 128;
    int bn = blockIdx.x * 128;
    sgemm_body<NC>(g_h, Wg, acc, bm, bn);

    int tx = threadIdx.x & 15;
    int ty = threadIdx.x >> 4;
#pragma unroll
    for (int i = 0; i < 8; i++) {
        int m = bm + ((i < 4) ? (ty * 4 + i) : (64 + ty * 4 + i - 4));
#pragma unroll
        for (int g = 0; g < 2; g++) {
            int n0 = bn + g * 64 + tx * 4;
            float4 bia = *(const float4*)&bg[n0];
            float4 h4  = *(const float4*)&g_h[(size_t)m * NC + n0];
            float4 o;
            o.x = h4.x * sigmoidf_(acc[i][g * 4 + 0] + bia.x);
            o.y = h4.y * sigmoidf_(acc[i][g * 4 + 1] + bia.y);
            o.z = h4.z * sigmoidf_(acc[i][g * 4 + 2] + bia.z);
            o.w = h4.w * sigmoidf_(acc[i][g * 4 + 3] + bia.w);
            *(float4*)&out[(size_t)m * NC + n0] = o;
        }
    }
}

// ---------------- launch ----------------
extern "C" void kernel_launch(void* const* d_in, const int* in_sizes, int n_in,
                              void* d_out, int out_size) {
    const float* x   = (const float*)d_in[0];
    const float* Wzf = (const float*)d_in[1];
    const float* bzf = (const float*)d_in[2];
    const float* Whf = (const float*)d_in[3];
    const float* bhf = (const float*)d_in[4];
    const float* Wzs = (const float*)d_in[5];
    const float* bzs = (const float*)d_in[6];
    const float* Whs = (const float*)d_in[7];
    const float* bhs = (const float*)d_in[8];
    const float* Wg  = (const float*)d_in[9];
    const float* bg  = (const float*)d_in[10];
    float* out = (float*)d_out;

    pack_w_kernel<<<(DIN * N1 + 255) / 256, 256>>>(Wzf, Whf, Wzs, Whs, bzf, bhf, bzs, bhs);
    gemm1_kernel<<<dim3(N1 / 128, M_ / 128), 256>>>(x);
    scan_phase1<<<dim3(LANES / 256, NCHUNK), 256>>>();
    scan_phase2<<<LANES / 256, 256>>>();
    scan_phase3<<<dim3(LANES / 256, NCHUNK), 256>>>();
    gemm2_kernel<<<dim3(NC / 128, M_ / 128), 256>>>(Wg, bg, out);
}

// round 3
// speedup vs baseline: 2.4095x; 2.4095x over previous
#include <cuda_runtime.h>
#include <cstdint>
#include <math.h>

// Problem constants
#define B_      4
#define S_      4096
#define DIN     1024
#define NC      1024
#define N1      2048
#define M_      (B_*S_)         // 16384
#define LANES   (B_*NC)         // 4096
#define NCHUNK  64
#define LC      (S_/NCHUNK)     // 64

// ---------------- scratch (static device globals) ----------------
__device__ float  g_W1T[(size_t)N1 * DIN];        // packed weights, [n][k] (k-major rows)
__device__ float  g_WgT[(size_t)NC * DIN];        // gate weights, [n][k]
__device__ float  g_b1[N1];
__device__ float  g_Y[(size_t)M_ * N1];           // interleaved (a,b) pairs for the scan
__device__ float  g_h[(size_t)M_ * NC];
__device__ float2 g_Agg[NCHUNK * LANES];
__device__ float  g_Carry[NCHUNK * LANES];

__device__ __forceinline__ float sigmoidf_(float x) { return 1.0f / (1.0f + __expf(-x)); }
__device__ __forceinline__ uint32_t f2tf(float f) {
    uint32_t r;
    asm("cvt.rna.tf32.f32 %0, %1;" : "=r"(r) : "f"(f));
    return r;
}

__device__ __forceinline__ void mma_tf32(float c[4],
                                         uint32_t a0, uint32_t a1, uint32_t a2, uint32_t a3,
                                         uint32_t b0, uint32_t b1) {
    asm volatile(
        "mma.sync.aligned.m16n8k8.row.col.f32.tf32.tf32.f32 "
        "{%0,%1,%2,%3}, {%4,%5,%6,%7}, {%8,%9}, {%0,%1,%2,%3};"
        : "+f"(c[0]), "+f"(c[1]), "+f"(c[2]), "+f"(c[3])
        : "r"(a0), "r"(a1), "r"(a2), "r"(a3), "r"(b0), "r"(b1));
}

// ---------------- weight transpose / pack ----------------
// which==0: dst=g_W1T ; which==1: dst=g_WgT
// dst[(nOff + nMul*c) * 1024 + k] = src[k * Cdim + c]
__global__ void transpose_pack_kernel(const float* __restrict__ src,
                                      int Cdim, int nMul, int nOff, int which) {
    __shared__ float sm[32][33];
    float* dst = which ? g_WgT : g_W1T;
    int c0 = blockIdx.x * 32;
    int k0 = blockIdx.y * 32;
    int tx = threadIdx.x, ty = threadIdx.y;
    sm[ty][tx] = src[(size_t)(k0 + ty) * Cdim + c0 + tx];
    __syncthreads();
    int n = nOff + nMul * (c0 + ty);
    dst[(size_t)n * 1024 + k0 + tx] = sm[tx][ty];
}

__global__ void pack_bias_kernel(const float* __restrict__ bzf, const float* __restrict__ bhf,
                                 const float* __restrict__ bzs, const float* __restrict__ bhs) {
    int n = blockIdx.x * 256 + threadIdx.x;
    if (n >= N1) return;
    int c = n >> 1, hp = n & 1;
    float v;
    if (c < 512) v = hp ? bhf[c]       : bzf[c];
    else         v = hp ? bhs[c - 512] : bzs[c - 512];
    g_b1[n] = v;
}

// ---------------- tf32 mma.sync GEMM: 128x128 CTA, BK=16, 4 warps (64x64 each) ----------------
// SMEM tile layout: [s][col] with s = k-within-chunk (0..15), stride 136 floats,
// element (row m, k s) stored at col = m ^ ((s & 12) << 1). Conflict-free for both the
// scatter stores and the mma fragment loads (bank = (8*s + col) & 31).
#define SSTRIDE 136

template <int MODE>   // 1 = GEMM1 (scan-coeff epilogue), 2 = GEMM2 (gated-output epilogue)
__device__ __forceinline__ void gemm_core(const float* __restrict__ A,
                                          const float* __restrict__ BT,
                                          const float* __restrict__ bias,
                                          float* __restrict__ Out) {
    __shared__ float As[2][16][SSTRIDE];
    __shared__ float Bs[2][16][SSTRIDE];

    const int tid  = threadIdx.x;
    const int lane = tid & 31, w = tid >> 5;
    const int g = lane >> 2, t = lane & 3;
    const int wm = (w & 1) * 64, wn = (w >> 1) * 64;
    const int bm = blockIdx.y * 128, bn = blockIdx.x * 128;
    const int mrow = tid >> 2;     // 0..31, +32*i
    const int kq   = tid & 3;      // k-quad

    const float* Ag = A  + (size_t)bm * 1024 + kq * 4;
    const float* Bg = BT + (size_t)bn * 1024 + kq * 4;

    float acc[4][8][4];
#pragma unroll
    for (int i = 0; i < 4; i++)
#pragma unroll
        for (int j = 0; j < 8; j++)
#pragma unroll
            for (int q = 0; q < 4; q++) acc[i][j][q] = 0.0f;

    float4 avA[4], avB[4];

#pragma unroll
    for (int i = 0; i < 4; i++) {
        int m = mrow + 32 * i;
        avA[i] = *(const float4*)(Ag + (size_t)m * 1024);
        avB[i] = *(const float4*)(Bg + (size_t)m * 1024);
    }

    for (int kt = 0; kt < 64; kt++) {
        int p = kt & 1;
        // store staged regs into smem (transposed + swizzled)
#pragma unroll
        for (int i = 0; i < 4; i++) {
            int m = mrow + 32 * i;
            int col = m ^ (kq << 3);
            As[p][kq * 4 + 0][col] = avA[i].x;
            As[p][kq * 4 + 1][col] = avA[i].y;
            As[p][kq * 4 + 2][col] = avA[i].z;
            As[p][kq * 4 + 3][col] = avA[i].w;
            Bs[p][kq * 4 + 0][col] = avB[i].x;
            Bs[p][kq * 4 + 1][col] = avB[i].y;
            Bs[p][kq * 4 + 2][col] = avB[i].z;
            Bs[p][kq * 4 + 3][col] = avB[i].w;
        }
        __syncthreads();
        if (kt < 63) {
#pragma unroll
            for (int i = 0; i < 4; i++) {
                int m = mrow + 32 * i;
                avA[i] = *(const float4*)(Ag + (size_t)m * 1024 + (kt + 1) * 16);
                avB[i] = *(const float4*)(Bg + (size_t)m * 1024 + (kt + 1) * 16);
            }
        }
        // compute on buffer p: two k8 steps (kk = 0, 8)
#pragma unroll
        for (int kk = 0; kk < 16; kk += 8) {
            const int X0 = kk * 2;       // xor const for s in [kk, kk+4)
            const int X1 = kk * 2 + 8;   // xor const for s in [kk+4, kk+8)
            uint32_t bf[8][2];
#pragma unroll
            for (int nt = 0; nt < 8; nt++) {
                int n = wn + nt * 8 + g;
                bf[nt][0] = f2tf(Bs[p][kk + t][n ^ X0]);
                bf[nt][1] = f2tf(Bs[p][kk + t + 4][n ^ X1]);
            }
#pragma unroll
            for (int mt = 0; mt < 4; mt++) {
                int m = wm + mt * 16 + g;
                uint32_t a0 = f2tf(As[p][kk + t][m ^ X0]);
                uint32_t a1 = f2tf(As[p][kk + t][(m + 8) ^ X0]);
                uint32_t a2 = f2tf(As[p][kk + t + 4][m ^ X1]);
                uint32_t a3 = f2tf(As[p][kk + t + 4][(m + 8) ^ X1]);
#pragma unroll
                for (int nt = 0; nt < 8; nt++)
                    mma_tf32(acc[mt][nt], a0, a1, a2, a3, bf[nt][0], bf[nt][1]);
            }
        }
        __syncthreads();
    }

    // ---------------- epilogue ----------------
    const int NOUT = (MODE == 1) ? N1 : NC;
#pragma unroll
    for (int mt = 0; mt < 4; mt++) {
#pragma unroll
        for (int nt = 0; nt < 8; nt++) {
            int row = bm + wm + mt * 16 + g;
            int col = bn + wn + nt * 8 + t * 2;       // even: (z, h~) pair
            float2 bb = *(const float2*)&bias[col];
            const float* a4 = acc[mt][nt];
            if (MODE == 1) {
                float z0 = sigmoidf_(a4[0] + bb.x);
                float h0 = a4[1] + bb.y;
                *(float2*)&Out[(size_t)row * NOUT + col] = make_float2(1.0f - z0, z0 * h0);
                float z1 = sigmoidf_(a4[2] + bb.x);
                float h1 = a4[3] + bb.y;
                *(float2*)&Out[(size_t)(row + 8) * NOUT + col] = make_float2(1.0f - z1, z1 * h1);
            } else {
                float2 hv0 = *(const float2*)&g_h[(size_t)row * NC + col];
                *(float2*)&Out[(size_t)row * NOUT + col] =
                    make_float2(hv0.x * sigmoidf_(a4[0] + bb.x),
                                hv0.y * sigmoidf_(a4[1] + bb.y));
                float2 hv1 = *(const float2*)&g_h[(size_t)(row + 8) * NC + col];
                *(float2*)&Out[(size_t)(row + 8) * NOUT + col] =
                    make_float2(hv1.x * sigmoidf_(a4[2] + bb.x),
                                hv1.y * sigmoidf_(a4[3] + bb.y));
            }
        }
    }
}

__global__ __launch_bounds__(128) void gemm1_mma(const float* __restrict__ x) {
    gemm_core<1>(x, g_W1T, g_b1, g_Y);
}
__global__ __launch_bounds__(128) void gemm2_mma(const float* __restrict__ bg,
                                                 float* __restrict__ out) {
    gemm_core<2>(g_h, g_WgT, bg, out);
}

// ---------------- scan (3-phase chunked) ----------------
__global__ __launch_bounds__(256) void scan_phase1() {
    int lane = blockIdx.x * blockDim.x + threadIdx.x;
    int j    = blockIdx.y;
    int b    = lane >> 10;
    int c    = lane & (NC - 1);
    const float2* Y2 = (const float2*)g_Y;
    size_t base = ((size_t)(b * S_ + j * LC)) * NC + c;
    float A = 1.0f, H = 0.0f;
#pragma unroll 8
    for (int t = 0; t < LC; t++) {
        float2 ab = Y2[base + (size_t)t * NC];
        A *= ab.x;
        H = fmaf(ab.x, H, ab.y);
    }
    g_Agg[j * LANES + lane] = make_float2(A, H);
}

__global__ __launch_bounds__(256) void scan_phase2() {
    int lane = blockIdx.x * blockDim.x + threadIdx.x;
    float carry = 0.0f;
#pragma unroll
    for (int j = 0; j < NCHUNK; j++) {
        float2 e = g_Agg[j * LANES + lane];
        g_Carry[j * LANES + lane] = carry;
        carry = fmaf(e.x, carry, e.y);
    }
}

__global__ __launch_bounds__(256) void scan_phase3() {
    int lane = blockIdx.x * blockDim.x + threadIdx.x;
    int j    = blockIdx.y;
    int b    = lane >> 10;
    int c    = lane & (NC - 1);
    const float2* Y2 = (const float2*)g_Y;
    size_t m0 = (size_t)(b * S_ + j * LC);
    size_t base = m0 * NC + c;
    float H = g_Carry[j * LANES + lane];
#pragma unroll 8
    for (int t = 0; t < LC; t++) {
        float2 ab = Y2[base + (size_t)t * NC];
        H = fmaf(ab.x, H, ab.y);
        g_h[(m0 + t) * NC + c] = H;
    }
}

// ---------------- launch ----------------
extern "C" void kernel_launch(void* const* d_in, const int* in_sizes, int n_in,
                              void* d_out, int out_size) {
    const float* x   = (const float*)d_in[0];
    const float* Wzf = (const float*)d_in[1];
    const float* bzf = (const float*)d_in[2];
    const float* Whf = (const float*)d_in[3];
    const float* bhf = (const float*)d_in[4];
    const float* Wzs = (const float*)d_in[5];
    const float* bzs = (const float*)d_in[6];
    const float* Whs = (const float*)d_in[7];
    const float* bhs = (const float*)d_in[8];
    const float* Wg  = (const float*)d_in[9];
    const float* bg  = (const float*)d_in[10];
    float* out = (float*)d_out;

    dim3 tb(32, 32);
    transpose_pack_kernel<<<dim3(16, 32), tb>>>(Wzf, 512, 2, 0, 0);
    transpose_pack_kernel<<<dim3(16, 32), tb>>>(Whf, 512, 2, 1, 0);
    transpose_pack_kernel<<<dim3(16, 32), tb>>>(Wzs, 512, 2, 1024, 0);
    transpose_pack_kernel<<<dim3(16, 32), tb>>>(Whs, 512, 2, 1025, 0);
    transpose_pack_kernel<<<dim3(32, 32), tb>>>(Wg, 1024, 1, 0, 1);
    pack_bias_kernel<<<N1 / 256, 256>>>(bzf, bhf, bzs, bhs);

    gemm1_mma<<<dim3(N1 / 128, M_ / 128), 128>>>(x);

    scan_phase1<<<dim3(LANES / 256, NCHUNK), 256>>>();
    scan_phase2<<<LANES / 256, 256>>>();
    scan_phase3<<<dim3(LANES / 256, NCHUNK), 256>>>();

    gemm2_mma<<<dim3(NC / 128, M_ / 128), 128>>>(bg, out);
}